// round 2
// baseline (speedup 1.0000x reference)
#include <cuda_runtime.h>
#include <math.h>

#define Bq 8
#define Tt 8192
#define Dd 128
#define Kk 64
#define BT (Bq*Tt)          // 65536
#define NC 128
#define CL (Tt/NC)          // 64

// ---- device scratch (static; no runtime alloc allowed) ----
__device__ float2 g_A[BT*Kk];          // 32 MB: a_t = rho*e^{i theta}
__device__ float  g_U[BT*Kk];          // 16 MB: u_t
__device__ float4 g_chunk[Bq*Kk*NC];   // per-chunk affine summary (A_re,A_im,z_re,z_im)
__device__ float2 g_zstart[Bq*Kk*NC];  // per-chunk initial state
__device__ float  g_G[Kk*Kk];          // Gram matrix W W^T
__device__ float  g_sigma_inv;
__device__ float  g_alpha0[Kk];
__device__ float  g_omega0[Kk];

__device__ __forceinline__ float softplusf(float x){
    return (x > 20.f) ? x : log1pf(expf(x));
}

// ---------------- K0a: G = W W^T  (+ alpha0/omega0 from tau) ----------------
__global__ void k0a_gram(const float* __restrict__ W,
                         const float* __restrict__ s_real_raw,
                         const float* __restrict__ s_imag,
                         const float* __restrict__ tau_raw)
{
    __shared__ float sW[64*132];            // padded stride 132 (bank-friendly)
    int tid = threadIdx.x;                  // 256 threads
    const float4* W4 = (const float4*)W;    // 2048 float4
    #pragma unroll
    for (int r = 0; r < 8; ++r) {
        int lin = tid + r*256;
        int k = lin >> 5, d4 = lin & 31;
        ((float4*)&sW[k*132])[d4] = W4[lin];
    }
    __syncthreads();
    int ti = tid >> 4, tj = tid & 15;
    float acc[4][4];
    #pragma unroll
    for (int a=0;a<4;a++){
        #pragma unroll
        for (int b2=0;b2<4;b2++) acc[a][b2]=0.f;
    }
    #pragma unroll 4
    for (int d4 = 0; d4 < 32; ++d4) {
        float4 av[4], bv[4];
        #pragma unroll
        for (int a=0;a<4;a++)  av[a] = ((const float4*)&sW[(ti*4+a)*132])[d4];
        #pragma unroll
        for (int b2=0;b2<4;b2++) bv[b2] = ((const float4*)&sW[(tj*4+b2)*132])[d4];
        #pragma unroll
        for (int a=0;a<4;a++){
            #pragma unroll
            for (int b2=0;b2<4;b2++){
                acc[a][b2] += av[a].x*bv[b2].x + av[a].y*bv[b2].y
                            + av[a].z*bv[b2].z + av[a].w*bv[b2].w;
            }
        }
    }
    #pragma unroll
    for (int a=0;a<4;a++){
        #pragma unroll
        for (int b2=0;b2<4;b2++)
            g_G[(ti*4+a)*64 + (tj*4+b2)] = acc[a][b2];
    }
    if (tid < 64) {
        float tau = softplusf(tau_raw[0]) + 1e-3f;
        g_alpha0[tid] = (softplusf(s_real_raw[tid]) + 1e-6f) * tau;
        g_omega0[tid] = s_imag[tid] * tau;
    }
}

// ---------------- K0b: 6 squarings + 64 power iters + Rayleigh ----------------
__global__ void k0b_sigma(const float* __restrict__ W)
{
    __shared__ float M[64*68];
    __shared__ float H[64*68];
    __shared__ float vbuf[2][64];
    __shared__ float red[64];
    __shared__ float red2[64];
    int tid = threadIdx.x;   // 256
    #pragma unroll
    for (int r = 0; r < 16; ++r) {
        int lin = tid + r*256;
        M[(lin>>6)*68 + (lin&63)] = g_G[lin];
    }
    __syncthreads();
    float* cur = M; float* oth = H;
    int ti = tid >> 4, tj = tid & 15;
    for (int sq = 0; sq < 6; ++sq) {
        float acc[4][4];
        #pragma unroll
        for (int a=0;a<4;a++){
            #pragma unroll
            for (int b2=0;b2<4;b2++) acc[a][b2]=0.f;
        }
        #pragma unroll 4
        for (int l = 0; l < 64; ++l) {
            float a0 = cur[(ti*4+0)*68 + l];
            float a1 = cur[(ti*4+1)*68 + l];
            float a2 = cur[(ti*4+2)*68 + l];
            float a3 = cur[(ti*4+3)*68 + l];
            float4 bv = *(const float4*)&cur[l*68 + tj*4];
            acc[0][0]+=a0*bv.x; acc[0][1]+=a0*bv.y; acc[0][2]+=a0*bv.z; acc[0][3]+=a0*bv.w;
            acc[1][0]+=a1*bv.x; acc[1][1]+=a1*bv.y; acc[1][2]+=a1*bv.z; acc[1][3]+=a1*bv.w;
            acc[2][0]+=a2*bv.x; acc[2][1]+=a2*bv.y; acc[2][2]+=a2*bv.z; acc[2][3]+=a2*bv.w;
            acc[3][0]+=a3*bv.x; acc[3][1]+=a3*bv.y; acc[3][2]+=a3*bv.z; acc[3][3]+=a3*bv.w;
        }
        #pragma unroll
        for (int a=0;a<4;a++){
            #pragma unroll
            for (int b2=0;b2<4;b2++)
                oth[(ti*4+a)*68 + tj*4+b2] = acc[a][b2];
        }
        __syncthreads();
        if (tid < 64) red[tid] = oth[tid*68 + tid];
        __syncthreads();
        for (int s = 32; s > 0; s >>= 1) {
            if (tid < s) red[tid] += red[tid+s];
            __syncthreads();
        }
        float sc = 1.0f / red[0];
        #pragma unroll
        for (int r = 0; r < 16; ++r) {
            int lin = tid + r*256;
            oth[(lin>>6)*68 + (lin&63)] *= sc;
        }
        __syncthreads();
        float* t = cur; cur = oth; oth = t;
    }
    // power iterations on cur (= G^64, trace-normalized)
    if (tid < 64) vbuf[0][tid] = 1.0f + 0.001f*(float)tid;
    __syncthreads();
    int i = tid >> 2, p = tid & 3;
    for (int it = 0; it < 64; ++it) {
        const float* v = vbuf[it & 1];
        float s = 0.f;
        #pragma unroll
        for (int l4 = 0; l4 < 4; ++l4) {
            int lb = p*16 + l4*4;
            float4 m = *(const float4*)&cur[i*68 + lb];
            s += m.x*v[lb] + m.y*v[lb+1] + m.z*v[lb+2] + m.w*v[lb+3];
        }
        s += __shfl_xor_sync(0xffffffffu, s, 1);
        s += __shfl_xor_sync(0xffffffffu, s, 2);
        if (p == 0) vbuf[(it+1)&1][i] = s;
        __syncthreads();
        if ((it & 3) == 3) {               // renormalize every 4 iters
            float* vn = vbuf[(it+1)&1];
            if (tid < 64) red[tid] = vn[tid]*vn[tid];
            __syncthreads();
            for (int st = 32; st > 0; st >>= 1) {
                if (tid < st) red[tid] += red[tid+st];
                __syncthreads();
            }
            float scl = rsqrtf(red[0]);
            if (tid < 64) vn[tid] *= scl;
            __syncthreads();
        }
    }
    // Rayleigh quotient with ORIGINAL G via W: lambda = v^T W W^T v / v^T v
    const float* vf = vbuf[0];
    float* tvec = H;   // reuse as 128-float scratch
    if (tid < 128) {
        float s = 0.f;
        #pragma unroll 4
        for (int k = 0; k < 64; ++k) s += W[k*128 + tid] * vf[k];
        tvec[tid] = s;
    }
    __syncthreads();
    if (tid < 64) {
        float s = 0.f;
        #pragma unroll 4
        for (int d = 0; d < 128; ++d) s += W[tid*128 + d] * tvec[d];
        red[tid]  = s * vf[tid];
        red2[tid] = vf[tid]*vf[tid];
    }
    __syncthreads();
    for (int st = 32; st > 0; st >>= 1) {
        if (tid < st) { red[tid] += red[tid+st]; red2[tid] += red2[tid+st]; }
        __syncthreads();
    }
    if (tid == 0) g_sigma_inv = rsqrtf(red[0] / red2[0]);
}

// ---------------- K1: fused GEMM (u = x W_sn^T + b) + pointwise a_t ----------------
__global__ void k1_gemm(const float* __restrict__ x,
                        const float* __restrict__ dt,
                        const float* __restrict__ alpha_mod,
                        const float* __restrict__ omega_mod,
                        const float* __restrict__ tau_mod,
                        const float* __restrict__ bvec,
                        const float* __restrict__ W)
{
    extern __shared__ float sm[];
    float* xs = sm;               // 128 rows x stride 132
    float* ws = sm + 128*132;     // 64 rows x stride 132
    int tid = threadIdx.x;        // 256
    int bt0 = blockIdx.x * 128;
    float siginv = g_sigma_inv;

    const float4* Wg4 = (const float4*)W;
    #pragma unroll
    for (int r = 0; r < 8; ++r) {
        int lin = tid + r*256;
        int k = lin >> 5, d4 = lin & 31;
        float4 w = Wg4[lin];
        w.x *= siginv; w.y *= siginv; w.z *= siginv; w.w *= siginv;
        ((float4*)&ws[k*132])[d4] = w;
    }
    const float4* xg4 = (const float4*)x + bt0*32;
    #pragma unroll
    for (int r = 0; r < 16; ++r) {
        int lin = tid + r*256;
        int i = lin >> 5, d4 = lin & 31;
        ((float4*)&xs[i*132])[d4] = xg4[lin];
    }
    __syncthreads();

    int kq = tid & 7, bq = tid >> 3;     // kq: 8 k-groups, bq: 32 bt-groups of 4
    float acc[4][8];
    #pragma unroll
    for (int a=0;a<4;a++){
        #pragma unroll
        for (int j=0;j<8;j++) acc[a][j]=0.f;
    }
    #pragma unroll 4
    for (int d4 = 0; d4 < 32; ++d4) {
        float4 xa[4], wb[8];
        #pragma unroll
        for (int a=0;a<4;a++) xa[a] = ((const float4*)&xs[(bq*4+a)*132])[d4];
        #pragma unroll
        for (int j=0;j<8;j++) wb[j] = ((const float4*)&ws[(kq+8*j)*132])[d4];
        #pragma unroll
        for (int a=0;a<4;a++){
            #pragma unroll
            for (int j=0;j<8;j++){
                acc[a][j] += xa[a].x*wb[j].x + xa[a].y*wb[j].y
                           + xa[a].z*wb[j].z + xa[a].w*wb[j].w;
            }
        }
    }
    #pragma unroll
    for (int a=0;a<4;a++) {
        int bt = bt0 + bq*4 + a;
        float dtv = dt[bt];
        float sc = expf(tau_mod[bt]);
        #pragma unroll
        for (int j=0;j<8;j++) {
            int k = kq + 8*j;
            int idx = bt*64 + k;
            float u  = acc[a][j] + bvec[k];
            float al = g_alpha0[k] * expf(alpha_mod[idx]) * sc;
            float om = g_omega0[k] * expf(omega_mod[idx]) * sc;
            float rho = expf(-al*dtv);
            float sn, cs;
            sincosf(om*dtv, &sn, &cs);
            g_A[idx] = make_float2(rho*cs, rho*sn);
            g_U[idx] = u;
        }
    }
}

// ---------------- K2: per-chunk affine summaries ----------------
__global__ void k2_chunks()
{
    int tid = threadIdx.x;               // 256
    int b  = blockIdx.x >> 5;
    int cg = blockIdx.x & 31;
    int k  = tid & 63;
    int chunk = cg*4 + (tid >> 6);
    int base = (b*Tt + chunk*CL)*Kk + k;
    float zr=0.f, zi=0.f, Ar=1.f, Ai=0.f;
    #pragma unroll 4
    for (int i = 0; i < CL; ++i) {
        float2 a = g_A[base + i*Kk];
        float u  = g_U[base + i*Kk];
        float nr = a.x*zr - a.y*zi + u;
        float ni = a.y*zr + a.x*zi;
        zr = nr; zi = ni;
        float br = a.x*Ar - a.y*Ai;
        float bi = a.y*Ar + a.x*Ai;
        Ar = br; Ai = bi;
    }
    g_chunk[(b*NC + chunk)*Kk + k] = make_float4(Ar, Ai, zr, zi);
}

// ---------------- K3: sequential combine across chunks (tiny) ----------------
__global__ void k3_combine()
{
    int tid = threadIdx.x;               // 512
    int b = tid >> 6, k = tid & 63;
    float zr = 0.f, zi = 0.f;
    for (int c = 0; c < NC; ++c) {
        int idx = (b*NC + c)*Kk + k;
        g_zstart[idx] = make_float2(zr, zi);
        float4 ch = g_chunk[idx];
        float nr = ch.x*zr - ch.y*zi + ch.z;
        float ni = ch.y*zr + ch.x*zi + ch.w;
        zr = nr; zi = ni;
    }
}

// ---------------- K4: final scan with correct init, write output ----------------
__global__ void k4_final(float* __restrict__ out)
{
    int tid = threadIdx.x;               // 256
    int b  = blockIdx.x >> 5;
    int cg = blockIdx.x & 31;
    int k  = tid & 63;
    int chunk = cg*4 + (tid >> 6);
    int t0 = chunk*CL;
    int base = (b*Tt + t0)*Kk + k;
    float2 z = g_zstart[(b*NC + chunk)*Kk + k];
    float zr = z.x, zi = z.y;
    float* outb = out + (size_t)(b*Tt + t0)*128;
    #pragma unroll 4
    for (int i = 0; i < CL; ++i) {
        float2 a = g_A[base + i*Kk];
        float u  = g_U[base + i*Kk];
        float nr = a.x*zr - a.y*zi + u;
        float ni = a.y*zr + a.x*zi;
        zr = nr; zi = ni;
        outb[i*128 + k]      = zr;   // C
        outb[i*128 + 64 + k] = zi;   // S
    }
}

extern "C" void kernel_launch(void* const* d_in, const int* in_sizes, int n_in,
                              void* d_out, int out_size)
{
    const float* x          = (const float*)d_in[0];
    const float* dt         = (const float*)d_in[1];
    const float* alpha_mod  = (const float*)d_in[2];
    const float* omega_mod  = (const float*)d_in[3];
    const float* tau_mod    = (const float*)d_in[4];
    const float* s_real_raw = (const float*)d_in[5];
    const float* s_imag     = (const float*)d_in[6];
    const float* tau_raw    = (const float*)d_in[7];
    const float* W          = (const float*)d_in[8];
    const float* bvec       = (const float*)d_in[9];
    float* out = (float*)d_out;

    cudaFuncSetAttribute(k1_gemm, cudaFuncAttributeMaxDynamicSharedMemorySize, 101376);

    k0a_gram<<<1, 256>>>(W, s_real_raw, s_imag, tau_raw);
    k0b_sigma<<<1, 256>>>(W);
    k1_gemm<<<512, 256, 101376>>>(x, dt, alpha_mod, omega_mod, tau_mod, bvec, W);
    k2_chunks<<<256, 256>>>();
    k3_combine<<<1, 512>>>();
    k4_final<<<256, 256>>>(out);
}

// round 3
// speedup vs baseline: 1.3960x; 1.3960x over previous
#include <cuda_runtime.h>
#include <math.h>

#define Bq 8
#define Tt 8192
#define Dd 128
#define Kk 64
#define BT (Bq*Tt)          // 65536
#define NC 256              // chunks per sequence
#define CL (Tt/NC)          // 32 steps per chunk

// ---- device scratch (static; no runtime alloc allowed) ----
__device__ float2 g_A[BT*Kk];          // 32 MB: a_t = rho*e^{i theta}
__device__ float  g_U[BT*Kk];          // 16 MB: u_t
__device__ float4 g_chunk[Bq*Kk*NC];   // per-chunk affine summary (A_re,A_im,z_re,z_im)
__device__ float2 g_zstart[Bq*Kk*NC];  // per-chunk initial state
__device__ float  g_G[Kk*Kk];          // Gram matrix W W^T
__device__ float  g_sigma_inv;
__device__ float  g_alpha0[Kk];
__device__ float  g_omega0[Kk];

__device__ __forceinline__ float softplusf(float x){
    return (x > 20.f) ? x : log1pf(expf(x));
}

// ---------------- K0a: G = W W^T  (+ alpha0/omega0 from tau) ----------------
__global__ void k0a_gram(const float* __restrict__ W,
                         const float* __restrict__ s_real_raw,
                         const float* __restrict__ s_imag,
                         const float* __restrict__ tau_raw)
{
    __shared__ float sW[64*132];
    int tid = threadIdx.x;                  // 256 threads
    const float4* W4 = (const float4*)W;    // 2048 float4
    #pragma unroll
    for (int r = 0; r < 8; ++r) {
        int lin = tid + r*256;
        int k = lin >> 5, d4 = lin & 31;
        ((float4*)&sW[k*132])[d4] = W4[lin];
    }
    __syncthreads();
    int ti = tid >> 4, tj = tid & 15;
    float acc[4][4];
    #pragma unroll
    for (int a=0;a<4;a++){
        #pragma unroll
        for (int b2=0;b2<4;b2++) acc[a][b2]=0.f;
    }
    #pragma unroll 4
    for (int d4 = 0; d4 < 32; ++d4) {
        float4 av[4], bv[4];
        #pragma unroll
        for (int a=0;a<4;a++)  av[a] = ((const float4*)&sW[(ti*4+a)*132])[d4];
        #pragma unroll
        for (int b2=0;b2<4;b2++) bv[b2] = ((const float4*)&sW[(tj*4+b2)*132])[d4];
        #pragma unroll
        for (int a=0;a<4;a++){
            #pragma unroll
            for (int b2=0;b2<4;b2++){
                acc[a][b2] += av[a].x*bv[b2].x + av[a].y*bv[b2].y
                            + av[a].z*bv[b2].z + av[a].w*bv[b2].w;
            }
        }
    }
    #pragma unroll
    for (int a=0;a<4;a++){
        #pragma unroll
        for (int b2=0;b2<4;b2++)
            g_G[(ti*4+a)*64 + (tj*4+b2)] = acc[a][b2];
    }
    if (tid < 64) {
        float tau = softplusf(tau_raw[0]) + 1e-3f;
        g_alpha0[tid] = (softplusf(s_real_raw[tid]) + 1e-6f) * tau;
        g_omega0[tid] = s_imag[tid] * tau;
    }
}

// ---------------- K0b: 6 squarings + 8 power iters + Rayleigh ----------------
__global__ void k0b_sigma(const float* __restrict__ W)
{
    __shared__ float M[64*68];
    __shared__ float H[64*68];
    __shared__ float vbuf[2][64];
    __shared__ float red[64];
    __shared__ float red2[64];
    int tid = threadIdx.x;   // 256
    #pragma unroll
    for (int r = 0; r < 16; ++r) {
        int lin = tid + r*256;
        M[(lin>>6)*68 + (lin&63)] = g_G[lin];
    }
    __syncthreads();
    float* cur = M; float* oth = H;
    int ti = tid >> 4, tj = tid & 15;
    for (int sq = 0; sq < 6; ++sq) {
        float acc[4][4];
        #pragma unroll
        for (int a=0;a<4;a++){
            #pragma unroll
            for (int b2=0;b2<4;b2++) acc[a][b2]=0.f;
        }
        #pragma unroll 4
        for (int l = 0; l < 64; ++l) {
            float a0 = cur[(ti*4+0)*68 + l];
            float a1 = cur[(ti*4+1)*68 + l];
            float a2 = cur[(ti*4+2)*68 + l];
            float a3 = cur[(ti*4+3)*68 + l];
            float4 bv = *(const float4*)&cur[l*68 + tj*4];
            acc[0][0]+=a0*bv.x; acc[0][1]+=a0*bv.y; acc[0][2]+=a0*bv.z; acc[0][3]+=a0*bv.w;
            acc[1][0]+=a1*bv.x; acc[1][1]+=a1*bv.y; acc[1][2]+=a1*bv.z; acc[1][3]+=a1*bv.w;
            acc[2][0]+=a2*bv.x; acc[2][1]+=a2*bv.y; acc[2][2]+=a2*bv.z; acc[2][3]+=a2*bv.w;
            acc[3][0]+=a3*bv.x; acc[3][1]+=a3*bv.y; acc[3][2]+=a3*bv.z; acc[3][3]+=a3*bv.w;
        }
        #pragma unroll
        for (int a=0;a<4;a++){
            #pragma unroll
            for (int b2=0;b2<4;b2++)
                oth[(ti*4+a)*68 + tj*4+b2] = acc[a][b2];
        }
        __syncthreads();
        if (tid < 64) red[tid] = oth[tid*68 + tid];
        __syncthreads();
        for (int s = 32; s > 0; s >>= 1) {
            if (tid < s) red[tid] += red[tid+s];
            __syncthreads();
        }
        float sc = 1.0f / red[0];
        #pragma unroll
        for (int r = 0; r < 16; ++r) {
            int lin = tid + r*256;
            oth[(lin>>6)*68 + (lin&63)] *= sc;
        }
        __syncthreads();
        float* t = cur; cur = oth; oth = t;
    }
    // 8 power iterations on cur (= G^64, trace-normalized); G^64 makes the
    // eigengap astronomically large, so 8 iterations >= 64 did before.
    if (tid < 64) vbuf[0][tid] = 1.0f + 0.001f*(float)tid;
    __syncthreads();
    int i = tid >> 2, p = tid & 3;
    for (int it = 0; it < 8; ++it) {
        const float* v = vbuf[it & 1];
        float s = 0.f;
        #pragma unroll
        for (int l4 = 0; l4 < 4; ++l4) {
            int lb = p*16 + l4*4;
            float4 m = *(const float4*)&cur[i*68 + lb];
            s += m.x*v[lb] + m.y*v[lb+1] + m.z*v[lb+2] + m.w*v[lb+3];
        }
        s += __shfl_xor_sync(0xffffffffu, s, 1);
        s += __shfl_xor_sync(0xffffffffu, s, 2);
        if (p == 0) vbuf[(it+1)&1][i] = s;
        __syncthreads();
        if ((it & 3) == 3) {               // renormalize every 4 iters
            float* vn = vbuf[(it+1)&1];
            if (tid < 64) red[tid] = vn[tid]*vn[tid];
            __syncthreads();
            for (int st = 32; st > 0; st >>= 1) {
                if (tid < st) red[tid] += red[tid+st];
                __syncthreads();
            }
            float scl = rsqrtf(red[0]);
            if (tid < 64) vn[tid] *= scl;
            __syncthreads();
        }
    }
    // Rayleigh quotient with ORIGINAL G via W: lambda = v^T W W^T v / v^T v
    const float* vf = vbuf[0];
    float* tvec = H;
    if (tid < 128) {
        float s = 0.f;
        #pragma unroll 4
        for (int k = 0; k < 64; ++k) s += W[k*128 + tid] * vf[k];
        tvec[tid] = s;
    }
    __syncthreads();
    if (tid < 64) {
        float s = 0.f;
        #pragma unroll 4
        for (int d = 0; d < 128; ++d) s += W[tid*128 + d] * tvec[d];
        red[tid]  = s * vf[tid];
        red2[tid] = vf[tid]*vf[tid];
    }
    __syncthreads();
    for (int st = 32; st > 0; st >>= 1) {
        if (tid < st) { red[tid] += red[tid+st]; red2[tid] += red2[tid+st]; }
        __syncthreads();
    }
    if (tid == 0) g_sigma_inv = rsqrtf(red[0] / red2[0]);
}

// ---- K1: fused GEMM (u = x W_sn^T + b) + pointwise a_t + CHUNK SUMMARIES ----
// Each block handles 128 consecutive time steps of one batch = 4 chunks of 32.
// After the GEMM, a/u are staged in smem (reusing the GEMM tile buffers) and
// the per-chunk affine summaries are computed in-block — this removes the
// 48MB re-read that the old k2_chunks kernel did.
__global__ void k1_gemm(const float* __restrict__ x,
                        const float* __restrict__ dt,
                        const float* __restrict__ alpha_mod,
                        const float* __restrict__ omega_mod,
                        const float* __restrict__ tau_mod,
                        const float* __restrict__ bvec,
                        const float* __restrict__ W)
{
    extern __shared__ float sm[];
    float* xs = sm;               // 128 rows x stride 132
    float* ws = sm + 128*132;     // 64 rows x stride 132
    int tid = threadIdx.x;        // 256
    int bt0 = blockIdx.x * 128;
    float siginv = g_sigma_inv;

    const float4* Wg4 = (const float4*)W;
    #pragma unroll
    for (int r = 0; r < 8; ++r) {
        int lin = tid + r*256;
        int k = lin >> 5, d4 = lin & 31;
        float4 w = Wg4[lin];
        w.x *= siginv; w.y *= siginv; w.z *= siginv; w.w *= siginv;
        ((float4*)&ws[k*132])[d4] = w;
    }
    const float4* xg4 = (const float4*)x + bt0*32;
    #pragma unroll
    for (int r = 0; r < 16; ++r) {
        int lin = tid + r*256;
        int i = lin >> 5, d4 = lin & 31;
        ((float4*)&xs[i*132])[d4] = xg4[lin];
    }
    __syncthreads();

    int kq = tid & 7, bq = tid >> 3;     // kq: 8 k-groups, bq: 32 bt-groups of 4
    float acc[4][8];
    #pragma unroll
    for (int a=0;a<4;a++){
        #pragma unroll
        for (int j=0;j<8;j++) acc[a][j]=0.f;
    }
    #pragma unroll 4
    for (int d4 = 0; d4 < 32; ++d4) {
        float4 xa[4], wb[8];
        #pragma unroll
        for (int a=0;a<4;a++) xa[a] = ((const float4*)&xs[(bq*4+a)*132])[d4];
        #pragma unroll
        for (int j=0;j<8;j++) wb[j] = ((const float4*)&ws[(kq+8*j)*132])[d4];
        #pragma unroll
        for (int a=0;a<4;a++){
            #pragma unroll
            for (int j=0;j<8;j++){
                acc[a][j] += xa[a].x*wb[j].x + xa[a].y*wb[j].y
                           + xa[a].z*wb[j].z + xa[a].w*wb[j].w;
            }
        }
    }
    __syncthreads();   // done reading xs/ws; reuse the buffer as a/u stage

    float* sAr = sm;                  // [128][65]
    float* sAi = sm + 128*65;
    float* sU  = sm + 2*128*65;

    #pragma unroll
    for (int a=0;a<4;a++) {
        int tl = bq*4 + a;            // local t in [0,128)
        int bt = bt0 + tl;
        float dtv = dt[bt];
        float sc = expf(tau_mod[bt]);
        #pragma unroll
        for (int j=0;j<8;j++) {
            int k = kq + 8*j;
            int idx = bt*64 + k;
            float u  = acc[a][j] + bvec[k];
            float al = g_alpha0[k] * expf(alpha_mod[idx]) * sc;
            float om = g_omega0[k] * expf(omega_mod[idx]) * sc;
            float rho = expf(-al*dtv);
            float sn, cs;
            sincosf(om*dtv, &sn, &cs);
            float ar = rho*cs, ai = rho*sn;
            g_A[idx] = make_float2(ar, ai);
            g_U[idx] = u;
            sAr[tl*65 + k] = ar;
            sAi[tl*65 + k] = ai;
            sU [tl*65 + k] = u;
        }
    }
    __syncthreads();

    // per-chunk scan: 256 threads = 4 chunks x 64 k lanes, 32 steps each
    {
        int cc = tid >> 6;            // local chunk 0..3
        int k  = tid & 63;
        int tb = cc*32;
        float zr=0.f, zi=0.f, Ar=1.f, Ai=0.f;
        #pragma unroll 8
        for (int i = 0; i < 32; ++i) {
            float ar = sAr[(tb+i)*65 + k];
            float ai = sAi[(tb+i)*65 + k];
            float u  = sU [(tb+i)*65 + k];
            float nr = ar*zr - ai*zi + u;
            float ni = ai*zr + ar*zi;
            zr = nr; zi = ni;
            float br = ar*Ar - ai*Ai;
            float bi = ai*Ar + ar*Ai;
            Ar = br; Ai = bi;
        }
        int b = blockIdx.x >> 6;
        int chunk = (blockIdx.x & 63)*4 + cc;
        g_chunk[(b*NC + chunk)*Kk + k] = make_float4(Ar, Ai, zr, zi);
    }
}

// ---------------- K3: combine across chunks, smem-staged ----------------
// 16 blocks = 8 batches x 2 k-halves. Parallel preload of all 256 chunk
// summaries into smem, then a 1-warp serial combine over LDS (29cy) instead
// of dependent DRAM loads (600cy).
__global__ void k3_combine()
{
    extern __shared__ float4 sc[];   // [256 chunks][32 k] = 128KB
    int b  = blockIdx.x >> 1;
    int kh = (blockIdx.x & 1) * 32;
    int tid = threadIdx.x;           // 256
    #pragma unroll
    for (int r = 0; r < 32; ++r) {
        int lin = tid + r*256;       // 0..8191
        int c = lin >> 5, k = lin & 31;
        sc[c*32 + k] = g_chunk[(b*NC + c)*Kk + kh + k];
    }
    __syncthreads();
    if (tid < 32) {
        int k = tid;
        float zr = 0.f, zi = 0.f;
        #pragma unroll 4
        for (int c = 0; c < NC; ++c) {
            g_zstart[(b*NC + c)*Kk + kh + k] = make_float2(zr, zi);
            float4 ch = sc[c*32 + k];
            float nr = ch.x*zr - ch.y*zi + ch.z;
            float ni = ch.y*zr + ch.x*zi + ch.w;
            zr = nr; zi = ni;
        }
    }
}

// ---------------- K4: final scan with correct init, write output ----------------
__global__ void k4_final(float* __restrict__ out)
{
    int tid = threadIdx.x;               // 256
    int b  = blockIdx.x >> 6;
    int cg = blockIdx.x & 63;
    int k  = tid & 63;
    int chunk = cg*4 + (tid >> 6);
    int t0 = chunk*CL;
    int base = (b*Tt + t0)*Kk + k;
    float2 z = g_zstart[(b*NC + chunk)*Kk + k];
    float zr = z.x, zi = z.y;
    float* outb = out + (size_t)(b*Tt + t0)*128;
    #pragma unroll 8
    for (int i = 0; i < CL; ++i) {
        float2 a = g_A[base + i*Kk];
        float u  = g_U[base + i*Kk];
        float nr = a.x*zr - a.y*zi + u;
        float ni = a.y*zr + a.x*zi;
        zr = nr; zi = ni;
        outb[i*128 + k]      = zr;   // C
        outb[i*128 + 64 + k] = zi;   // S
    }
}

extern "C" void kernel_launch(void* const* d_in, const int* in_sizes, int n_in,
                              void* d_out, int out_size)
{
    const float* x          = (const float*)d_in[0];
    const float* dt         = (const float*)d_in[1];
    const float* alpha_mod  = (const float*)d_in[2];
    const float* omega_mod  = (const float*)d_in[3];
    const float* tau_mod    = (const float*)d_in[4];
    const float* s_real_raw = (const float*)d_in[5];
    const float* s_imag     = (const float*)d_in[6];
    const float* tau_raw    = (const float*)d_in[7];
    const float* W          = (const float*)d_in[8];
    const float* bvec       = (const float*)d_in[9];
    float* out = (float*)d_out;

    static int attr_done = 0;
    if (!attr_done) {
        cudaFuncSetAttribute(k1_gemm,    cudaFuncAttributeMaxDynamicSharedMemorySize, 101376);
        cudaFuncSetAttribute(k3_combine, cudaFuncAttributeMaxDynamicSharedMemorySize, 131072);
        attr_done = 1;
    }

    k0a_gram<<<1, 256>>>(W, s_real_raw, s_imag, tau_raw);
    k0b_sigma<<<1, 256>>>(W);
    k1_gemm<<<512, 256, 101376>>>(x, dt, alpha_mod, omega_mod, tau_mod, bvec, W);
    k3_combine<<<16, 256, 131072>>>();
    k4_final<<<512, 256>>>(out);
}

// round 4
// speedup vs baseline: 1.7479x; 1.2521x over previous
#include <cuda_runtime.h>
#include <math.h>

#define Bq 8
#define Tt 8192
#define Dd 128
#define Kk 64
#define BT (Bq*Tt)          // 65536
#define NC 256              // chunks per sequence
#define CL (Tt/NC)          // 32 steps per chunk

// ---- device scratch (static; no runtime alloc allowed) ----
__device__ float2 g_A[BT*Kk];          // 32 MB: a_t = rho*e^{i theta}
__device__ float  g_U[BT*Kk];          // 16 MB: u_t
__device__ float4 g_chunk[Bq*Kk*NC];   // per-chunk affine summary, layout [b][k][c]
__device__ float2 g_zstart[Bq*Kk*NC];  // per-chunk initial state, layout [b][c][k]
__device__ float  g_sigma_inv;
__device__ float  g_alpha0[Kk];
__device__ float  g_omega0[Kk];

__device__ __forceinline__ float softplusf(float x){
    return (x > 20.f) ? x : log1pf(expf(x));
}

// ---------------- K0: Gram + 6 squarings + 8 power iters + Rayleigh ----------
// Single block. G = W W^T computed into smem; repeated squaring raises it to
// G^64 (trace-normalized), making the eigengap huge, so 8 power iterations
// suffice; final Rayleigh quotient against the ORIGINAL G (via W in smem)
// recovers sigma_max^2 to ~1e-4 rel regardless of spectral gap.
__global__ void k0_sigma(const float* __restrict__ W,
                         const float* __restrict__ s_real_raw,
                         const float* __restrict__ s_imag,
                         const float* __restrict__ tau_raw)
{
    extern __shared__ float dsm[];
    float* sW = dsm;              // 64 x 132 (padded)
    float* M  = dsm + 64*132;     // 64 x 68
    float* H  = dsm + 64*132 + 64*68;
    __shared__ float vbuf[2][64];
    __shared__ float red[64];
    __shared__ float red2[64];

    int tid = threadIdx.x;   // 256
    if (tid < 64) {
        float tau = softplusf(tau_raw[0]) + 1e-3f;
        g_alpha0[tid] = (softplusf(s_real_raw[tid]) + 1e-6f) * tau;
        g_omega0[tid] = s_imag[tid] * tau;
    }
    const float4* W4 = (const float4*)W;    // 2048 float4
    #pragma unroll
    for (int r = 0; r < 8; ++r) {
        int lin = tid + r*256;
        int k = lin >> 5, d4 = lin & 31;
        ((float4*)&sW[k*132])[d4] = W4[lin];
    }
    __syncthreads();

    // Gram: M = W W^T  (64x64), 4x4 per thread
    int ti = tid >> 4, tj = tid & 15;
    {
        float acc[4][4];
        #pragma unroll
        for (int a=0;a<4;a++){
            #pragma unroll
            for (int b2=0;b2<4;b2++) acc[a][b2]=0.f;
        }
        #pragma unroll 4
        for (int d4 = 0; d4 < 32; ++d4) {
            float4 av[4], bv[4];
            #pragma unroll
            for (int a=0;a<4;a++)  av[a] = ((const float4*)&sW[(ti*4+a)*132])[d4];
            #pragma unroll
            for (int b2=0;b2<4;b2++) bv[b2] = ((const float4*)&sW[(tj*4+b2)*132])[d4];
            #pragma unroll
            for (int a=0;a<4;a++){
                #pragma unroll
                for (int b2=0;b2<4;b2++){
                    acc[a][b2] += av[a].x*bv[b2].x + av[a].y*bv[b2].y
                                + av[a].z*bv[b2].z + av[a].w*bv[b2].w;
                }
            }
        }
        #pragma unroll
        for (int a=0;a<4;a++){
            #pragma unroll
            for (int b2=0;b2<4;b2++)
                M[(ti*4+a)*68 + (tj*4+b2)] = acc[a][b2];
        }
    }
    __syncthreads();

    float* cur = M; float* oth = H;
    for (int sq = 0; sq < 6; ++sq) {
        float acc[4][4];
        #pragma unroll
        for (int a=0;a<4;a++){
            #pragma unroll
            for (int b2=0;b2<4;b2++) acc[a][b2]=0.f;
        }
        #pragma unroll 4
        for (int l = 0; l < 64; ++l) {
            float a0 = cur[(ti*4+0)*68 + l];
            float a1 = cur[(ti*4+1)*68 + l];
            float a2 = cur[(ti*4+2)*68 + l];
            float a3 = cur[(ti*4+3)*68 + l];
            float4 bv = *(const float4*)&cur[l*68 + tj*4];
            acc[0][0]+=a0*bv.x; acc[0][1]+=a0*bv.y; acc[0][2]+=a0*bv.z; acc[0][3]+=a0*bv.w;
            acc[1][0]+=a1*bv.x; acc[1][1]+=a1*bv.y; acc[1][2]+=a1*bv.z; acc[1][3]+=a1*bv.w;
            acc[2][0]+=a2*bv.x; acc[2][1]+=a2*bv.y; acc[2][2]+=a2*bv.z; acc[2][3]+=a2*bv.w;
            acc[3][0]+=a3*bv.x; acc[3][1]+=a3*bv.y; acc[3][2]+=a3*bv.z; acc[3][3]+=a3*bv.w;
        }
        #pragma unroll
        for (int a=0;a<4;a++){
            #pragma unroll
            for (int b2=0;b2<4;b2++)
                oth[(ti*4+a)*68 + tj*4+b2] = acc[a][b2];
        }
        __syncthreads();
        if (tid < 64) red[tid] = oth[tid*68 + tid];
        __syncthreads();
        for (int s = 32; s > 0; s >>= 1) {
            if (tid < s) red[tid] += red[tid+s];
            __syncthreads();
        }
        float sc = 1.0f / red[0];
        #pragma unroll
        for (int r = 0; r < 16; ++r) {
            int lin = tid + r*256;
            oth[(lin>>6)*68 + (lin&63)] *= sc;
        }
        __syncthreads();
        float* t = cur; cur = oth; oth = t;
    }
    // cur == M here (6 swaps). 8 power iterations.
    if (tid < 64) vbuf[0][tid] = 1.0f + 0.001f*(float)tid;
    __syncthreads();
    int i = tid >> 2, p = tid & 3;
    for (int it = 0; it < 8; ++it) {
        const float* v = vbuf[it & 1];
        float s = 0.f;
        #pragma unroll
        for (int l4 = 0; l4 < 4; ++l4) {
            int lb = p*16 + l4*4;
            float4 m = *(const float4*)&cur[i*68 + lb];
            s += m.x*v[lb] + m.y*v[lb+1] + m.z*v[lb+2] + m.w*v[lb+3];
        }
        s += __shfl_xor_sync(0xffffffffu, s, 1);
        s += __shfl_xor_sync(0xffffffffu, s, 2);
        if (p == 0) vbuf[(it+1)&1][i] = s;
        __syncthreads();
        if ((it & 3) == 3) {
            float* vn = vbuf[(it+1)&1];
            if (tid < 64) red[tid] = vn[tid]*vn[tid];
            __syncthreads();
            for (int st = 32; st > 0; st >>= 1) {
                if (tid < st) red[tid] += red[tid+st];
                __syncthreads();
            }
            float scl = rsqrtf(red[0]);
            if (tid < 64) vn[tid] *= scl;
            __syncthreads();
        }
    }
    // Rayleigh quotient vs original G via sW: lambda = |W^T v|^2 / |v|^2
    const float* vf = vbuf[0];
    float* tvec = oth;   // oth == H, free
    if (tid < 128) {
        float s = 0.f;
        #pragma unroll 4
        for (int k = 0; k < 64; ++k) s += sW[k*132 + tid] * vf[k];
        tvec[tid] = s;
    }
    __syncthreads();
    if (tid < 64) {
        float s = 0.f;
        #pragma unroll 4
        for (int d = 0; d < 128; ++d) s += sW[tid*132 + d] * tvec[d];
        red[tid]  = s * vf[tid];
        red2[tid] = vf[tid]*vf[tid];
    }
    __syncthreads();
    for (int st = 32; st > 0; st >>= 1) {
        if (tid < st) { red[tid] += red[tid+st]; red2[tid] += red2[tid+st]; }
        __syncthreads();
    }
    if (tid == 0) g_sigma_inv = rsqrtf(red[0] / red2[0]);
}

// ---- K1: fused GEMM (u = x W_sn^T + b) + pointwise a_t + chunk summaries ----
// Pointwise path: alpha*dt and theta are tiny (<= ~2e-3), so exp(-x)/cos/sin
// are 3-term Taylor polynomials (error ~1e-12); only the two exp(mod) calls
// use MUFU (__expf). This removes the accurate-sincosf instruction avalanche.
__global__ void k1_gemm(const float* __restrict__ x,
                        const float* __restrict__ dt,
                        const float* __restrict__ alpha_mod,
                        const float* __restrict__ omega_mod,
                        const float* __restrict__ tau_mod,
                        const float* __restrict__ bvec,
                        const float* __restrict__ W)
{
    extern __shared__ float sm[];
    float* xs = sm;               // 128 rows x stride 132
    float* ws = sm + 128*132;     // 64 rows x stride 132
    int tid = threadIdx.x;        // 256
    int bt0 = blockIdx.x * 128;
    float siginv = g_sigma_inv;

    const float4* Wg4 = (const float4*)W;
    #pragma unroll
    for (int r = 0; r < 8; ++r) {
        int lin = tid + r*256;
        int k = lin >> 5, d4 = lin & 31;
        float4 w = Wg4[lin];
        w.x *= siginv; w.y *= siginv; w.z *= siginv; w.w *= siginv;
        ((float4*)&ws[k*132])[d4] = w;
    }
    const float4* xg4 = (const float4*)x + bt0*32;
    #pragma unroll
    for (int r = 0; r < 16; ++r) {
        int lin = tid + r*256;
        int i = lin >> 5, d4 = lin & 31;
        ((float4*)&xs[i*132])[d4] = xg4[lin];
    }
    __syncthreads();

    int kq = tid & 7, bq = tid >> 3;     // kq: 8 k-groups, bq: 32 bt-groups of 4
    float acc[4][8];
    #pragma unroll
    for (int a=0;a<4;a++){
        #pragma unroll
        for (int j=0;j<8;j++) acc[a][j]=0.f;
    }
    #pragma unroll 4
    for (int d4 = 0; d4 < 32; ++d4) {
        float4 xa[4], wb[8];
        #pragma unroll
        for (int a=0;a<4;a++) xa[a] = ((const float4*)&xs[(bq*4+a)*132])[d4];
        #pragma unroll
        for (int j=0;j<8;j++) wb[j] = ((const float4*)&ws[(kq+8*j)*132])[d4];
        #pragma unroll
        for (int a=0;a<4;a++){
            #pragma unroll
            for (int j=0;j<8;j++){
                acc[a][j] += xa[a].x*wb[j].x + xa[a].y*wb[j].y
                           + xa[a].z*wb[j].z + xa[a].w*wb[j].w;
            }
        }
    }
    __syncthreads();   // done reading xs/ws; reuse the buffer as a/u stage

    float* sAr = sm;                  // [128][65]
    float* sAi = sm + 128*65;
    float* sU  = sm + 2*128*65;

    #pragma unroll
    for (int a=0;a<4;a++) {
        int tl = bq*4 + a;            // local t in [0,128)
        int bt = bt0 + tl;
        float dtv = dt[bt];
        float tm  = tau_mod[bt];
        #pragma unroll
        for (int j=0;j<8;j++) {
            int k = kq + 8*j;
            int idx = bt*64 + k;
            float u  = acc[a][j] + bvec[k];
            float ad = g_alpha0[k] * __expf(alpha_mod[idx] + tm) * dtv; // alpha*dt
            float th = g_omega0[k] * __expf(omega_mod[idx] + tm) * dtv; // theta
            // |ad|,|th| <= ~2e-3: Taylor to machine precision
            float rho = 1.f - ad*(1.f - ad*(0.5f - 0.16666667f*ad));
            float t2  = th*th;
            float cs  = 1.f - 0.5f*t2*(1.f - 0.083333336f*t2);
            float sn  = th*(1.f - 0.16666667f*t2);
            float ar = rho*cs, ai = rho*sn;
            g_A[idx] = make_float2(ar, ai);
            g_U[idx] = u;
            sAr[tl*65 + k] = ar;
            sAi[tl*65 + k] = ai;
            sU [tl*65 + k] = u;
        }
    }
    __syncthreads();

    // per-chunk scan: 256 threads = 4 chunks x 64 k lanes, 32 steps each
    {
        int cc = tid >> 6;            // local chunk 0..3
        int k  = tid & 63;
        int tb = cc*32;
        float zr=0.f, zi=0.f, Ar=1.f, Ai=0.f;
        #pragma unroll 8
        for (int i = 0; i < 32; ++i) {
            float ar = sAr[(tb+i)*65 + k];
            float ai = sAi[(tb+i)*65 + k];
            float u  = sU [(tb+i)*65 + k];
            float nr = ar*zr - ai*zi + u;
            float ni = ai*zr + ar*zi;
            zr = nr; zi = ni;
            float br = ar*Ar - ai*Ai;
            float bi = ai*Ar + ar*Ai;
            Ar = br; Ai = bi;
        }
        int b = blockIdx.x >> 6;
        int chunk = (blockIdx.x & 63)*4 + cc;
        g_chunk[(b*Kk + k)*NC + chunk] = make_float4(Ar, Ai, zr, zi);
    }
}

// ---------------- K3: parallel inter-chunk scan ----------------
// One block per (b,k) lane: 512 blocks x 256 threads (one thread per chunk).
// Hillis-Steele scan of the affine composition in smem (8 steps).
__global__ void k3_combine()
{
    __shared__ float4 s[NC];
    int b = blockIdx.x >> 6;
    int k = blockIdx.x & 63;
    int c = threadIdx.x;             // chunk index
    float4 cur = g_chunk[(b*Kk + k)*NC + c];   // coalesced
    #pragma unroll
    for (int off = 1; off < NC; off <<= 1) {
        s[c] = cur;
        __syncthreads();
        if (c >= off) {
            float4 p = s[c - off];   // earlier prefix
            float Ar = cur.x*p.x - cur.y*p.y;
            float Ai = cur.x*p.y + cur.y*p.x;
            float ur = cur.x*p.z - cur.y*p.w + cur.z;
            float ui = cur.y*p.z + cur.x*p.w + cur.w;
            cur = make_float4(Ar, Ai, ur, ui);
        }
        __syncthreads();
    }
    s[c] = cur;
    __syncthreads();
    float zr = 0.f, zi = 0.f;
    if (c > 0) { zr = s[c-1].z; zi = s[c-1].w; }
    g_zstart[(b*NC + c)*Kk + k] = make_float2(zr, zi);
}

// ---------------- K4: final scan with correct init, write output ----------------
__global__ void k4_final(float* __restrict__ out)
{
    int tid = threadIdx.x;               // 256
    int b  = blockIdx.x >> 6;
    int cg = blockIdx.x & 63;
    int k  = tid & 63;
    int chunk = cg*4 + (tid >> 6);
    int t0 = chunk*CL;
    int base = (b*Tt + t0)*Kk + k;
    float2 z = g_zstart[(b*NC + chunk)*Kk + k];
    float zr = z.x, zi = z.y;
    float* outb = out + (size_t)(b*Tt + t0)*128;
    #pragma unroll 8
    for (int i = 0; i < CL; ++i) {
        float2 a = g_A[base + i*Kk];
        float u  = g_U[base + i*Kk];
        float nr = a.x*zr - a.y*zi + u;
        float ni = a.y*zr + a.x*zi;
        zr = nr; zi = ni;
        outb[i*128 + k]      = zr;   // C
        outb[i*128 + 64 + k] = zi;   // S
    }
}

extern "C" void kernel_launch(void* const* d_in, const int* in_sizes, int n_in,
                              void* d_out, int out_size)
{
    const float* x          = (const float*)d_in[0];
    const float* dt         = (const float*)d_in[1];
    const float* alpha_mod  = (const float*)d_in[2];
    const float* omega_mod  = (const float*)d_in[3];
    const float* tau_mod    = (const float*)d_in[4];
    const float* s_real_raw = (const float*)d_in[5];
    const float* s_imag     = (const float*)d_in[6];
    const float* tau_raw    = (const float*)d_in[7];
    const float* W          = (const float*)d_in[8];
    const float* bvec       = (const float*)d_in[9];
    float* out = (float*)d_out;

    cudaFuncSetAttribute(k0_sigma, cudaFuncAttributeMaxDynamicSharedMemorySize, 69632);
    cudaFuncSetAttribute(k1_gemm,  cudaFuncAttributeMaxDynamicSharedMemorySize, 101376);

    k0_sigma<<<1, 256, 69632>>>(W, s_real_raw, s_imag, tau_raw);
    k1_gemm<<<512, 256, 101376>>>(x, dt, alpha_mod, omega_mod, tau_mod, bvec, W);
    k3_combine<<<512, 256>>>();
    k4_final<<<512, 256>>>(out);
}

// round 5
// speedup vs baseline: 1.9050x; 1.0899x over previous
#include <cuda_runtime.h>
#include <math.h>

#define Bq 8
#define Tt 8192
#define Dd 128
#define Kk 64
#define BT (Bq*Tt)          // 65536
#define NBLK 512            // pipeline blocks
#define TPB 128             // timesteps per block
#define SEQB 64             // pipeline blocks per batch sequence

// ---- device scratch (static; no runtime alloc allowed) ----
__device__ float2 g_bA[NBLK*Kk];    // block aggregate multiplier  (per lane)
__device__ float2 g_bZ[NBLK*Kk];    // block aggregate offset (local scan result)
__device__ float2 g_bZI[NBLK*Kk];   // block inclusive prefix state
__device__ int    g_bst[NBLK];      // 0=invalid 1=aggregate 2=inclusive
__device__ int    g_sflag;          // sigma ready flag
__device__ float  g_sigma_inv;
__device__ float  g_alpha0[Kk];
__device__ float  g_omega0[Kk];

__device__ __forceinline__ float softplusf(float x){
    return (x > 20.f) ? x : log1pf(expf(x));
}

// -------- init: reset lookback statuses + sigma flag (runs every launch) ----
__global__ void k_init()
{
    int t = threadIdx.x;
    if (t < NBLK) g_bst[t] = 0;
    if (t == 0)   g_sflag  = 0;
}

// ============================ fused kernel ==================================
// block 0: sigma (Gram -> 6 squarings -> 8 power iters -> Rayleigh)
// blocks 1..512: GEMM + pointwise + single-pass chunked scan (decoupled
// lookback) + output. a/u never leave shared memory.
__global__ void __launch_bounds__(256, 2)
k_fused(const float* __restrict__ x,
        const float* __restrict__ dt,
        const float* __restrict__ alpha_mod,
        const float* __restrict__ omega_mod,
        const float* __restrict__ tau_mod,
        const float* __restrict__ bvec,
        const float* __restrict__ W,
        const float* __restrict__ s_real_raw,
        const float* __restrict__ s_imag,
        const float* __restrict__ tau_raw,
        float* __restrict__ out)
{
    extern __shared__ float sm[];
    int tid = threadIdx.x;   // 256

    if (blockIdx.x == 0) {
        // ------------------------- sigma block ------------------------------
        float* sW = sm;               // 64 x 132
        float* M  = sm + 64*132;      // 64 x 68
        float* H  = sm + 64*132 + 64*68;
        __shared__ float vbuf[2][64];
        __shared__ float red[64];
        __shared__ float red2[64];

        if (tid < 64) {
            float tau = softplusf(tau_raw[0]) + 1e-3f;
            g_alpha0[tid] = (softplusf(s_real_raw[tid]) + 1e-6f) * tau;
            g_omega0[tid] = s_imag[tid] * tau;
        }
        const float4* W4 = (const float4*)W;
        #pragma unroll
        for (int r = 0; r < 8; ++r) {
            int lin = tid + r*256;
            int k = lin >> 5, d4 = lin & 31;
            ((float4*)&sW[k*132])[d4] = W4[lin];
        }
        __syncthreads();

        int ti = tid >> 4, tj = tid & 15;
        {   // Gram
            float acc[4][4];
            #pragma unroll
            for (int a=0;a<4;a++){
                #pragma unroll
                for (int b2=0;b2<4;b2++) acc[a][b2]=0.f;
            }
            #pragma unroll 4
            for (int d4 = 0; d4 < 32; ++d4) {
                float4 av[4], bv[4];
                #pragma unroll
                for (int a=0;a<4;a++)  av[a] = ((const float4*)&sW[(ti*4+a)*132])[d4];
                #pragma unroll
                for (int b2=0;b2<4;b2++) bv[b2] = ((const float4*)&sW[(tj*4+b2)*132])[d4];
                #pragma unroll
                for (int a=0;a<4;a++){
                    #pragma unroll
                    for (int b2=0;b2<4;b2++){
                        acc[a][b2] += av[a].x*bv[b2].x + av[a].y*bv[b2].y
                                    + av[a].z*bv[b2].z + av[a].w*bv[b2].w;
                    }
                }
            }
            #pragma unroll
            for (int a=0;a<4;a++){
                #pragma unroll
                for (int b2=0;b2<4;b2++)
                    M[(ti*4+a)*68 + (tj*4+b2)] = acc[a][b2];
            }
        }
        __syncthreads();

        float* cur = M; float* oth = H;
        for (int sq = 0; sq < 6; ++sq) {
            float acc[4][4];
            #pragma unroll
            for (int a=0;a<4;a++){
                #pragma unroll
                for (int b2=0;b2<4;b2++) acc[a][b2]=0.f;
            }
            #pragma unroll 4
            for (int l = 0; l < 64; ++l) {
                float a0 = cur[(ti*4+0)*68 + l];
                float a1 = cur[(ti*4+1)*68 + l];
                float a2 = cur[(ti*4+2)*68 + l];
                float a3 = cur[(ti*4+3)*68 + l];
                float4 bv = *(const float4*)&cur[l*68 + tj*4];
                acc[0][0]+=a0*bv.x; acc[0][1]+=a0*bv.y; acc[0][2]+=a0*bv.z; acc[0][3]+=a0*bv.w;
                acc[1][0]+=a1*bv.x; acc[1][1]+=a1*bv.y; acc[1][2]+=a1*bv.z; acc[1][3]+=a1*bv.w;
                acc[2][0]+=a2*bv.x; acc[2][1]+=a2*bv.y; acc[2][2]+=a2*bv.z; acc[2][3]+=a2*bv.w;
                acc[3][0]+=a3*bv.x; acc[3][1]+=a3*bv.y; acc[3][2]+=a3*bv.z; acc[3][3]+=a3*bv.w;
            }
            #pragma unroll
            for (int a=0;a<4;a++){
                #pragma unroll
                for (int b2=0;b2<4;b2++)
                    oth[(ti*4+a)*68 + tj*4+b2] = acc[a][b2];
            }
            __syncthreads();
            if (tid < 64) red[tid] = oth[tid*68 + tid];
            __syncthreads();
            for (int s = 32; s > 0; s >>= 1) {
                if (tid < s) red[tid] += red[tid+s];
                __syncthreads();
            }
            float sc = 1.0f / red[0];
            #pragma unroll
            for (int r = 0; r < 16; ++r) {
                int lin = tid + r*256;
                oth[(lin>>6)*68 + (lin&63)] *= sc;
            }
            __syncthreads();
            float* t = cur; cur = oth; oth = t;
        }
        if (tid < 64) vbuf[0][tid] = 1.0f + 0.001f*(float)tid;
        __syncthreads();
        int i = tid >> 2, p = tid & 3;
        for (int it = 0; it < 8; ++it) {
            const float* v = vbuf[it & 1];
            float s = 0.f;
            #pragma unroll
            for (int l4 = 0; l4 < 4; ++l4) {
                int lb = p*16 + l4*4;
                float4 m = *(const float4*)&cur[i*68 + lb];
                s += m.x*v[lb] + m.y*v[lb+1] + m.z*v[lb+2] + m.w*v[lb+3];
            }
            s += __shfl_xor_sync(0xffffffffu, s, 1);
            s += __shfl_xor_sync(0xffffffffu, s, 2);
            if (p == 0) vbuf[(it+1)&1][i] = s;
            __syncthreads();
            if ((it & 3) == 3) {
                float* vn = vbuf[(it+1)&1];
                if (tid < 64) red[tid] = vn[tid]*vn[tid];
                __syncthreads();
                for (int st = 32; st > 0; st >>= 1) {
                    if (tid < st) red[tid] += red[tid+st];
                    __syncthreads();
                }
                float scl = rsqrtf(red[0]);
                if (tid < 64) vn[tid] *= scl;
                __syncthreads();
            }
        }
        const float* vf = vbuf[0];
        float* tvec = oth;
        if (tid < 128) {
            float s = 0.f;
            #pragma unroll 4
            for (int kk = 0; kk < 64; ++kk) s += sW[kk*132 + tid] * vf[kk];
            tvec[tid] = s;
        }
        __syncthreads();
        if (tid < 64) {
            float s = 0.f;
            #pragma unroll 4
            for (int d = 0; d < 128; ++d) s += sW[tid*132 + d] * tvec[d];
            red[tid]  = s * vf[tid];
            red2[tid] = vf[tid]*vf[tid];
        }
        __syncthreads();
        for (int st = 32; st > 0; st >>= 1) {
            if (tid < st) { red[tid] += red[tid+st]; red2[tid] += red2[tid+st]; }
            __syncthreads();
        }
        if (tid == 0) {
            g_sigma_inv = rsqrtf(red[0] / red2[0]);
            __threadfence();
            atomicExch(&g_sflag, 1);
        }
        return;
    }

    // ------------------------- pipeline blocks ------------------------------
    __shared__ float4 sSum[4*64];     // per-sub-chunk summaries
    __shared__ float2 sPre[64];       // per-lane prefix entering this block
    __shared__ int    s_st;

    int lin = blockIdx.x - 1;         // 0..511
    int p   = lin & (SEQB-1);         // position within sequence
    int bt0 = lin * TPB;

    float* xs = sm;                   // 128 rows x stride 132
    float* ws = sm + 128*132;         // 64 rows x stride 132 (raw W, no sigma)

    const float4* Wg4 = (const float4*)W;
    #pragma unroll
    for (int r = 0; r < 8; ++r) {
        int l = tid + r*256;
        int k2 = l >> 5, d4 = l & 31;
        ((float4*)&ws[k2*132])[d4] = Wg4[l];
    }
    const float4* xg4 = (const float4*)x + (size_t)bt0*32;
    #pragma unroll
    for (int r = 0; r < 16; ++r) {
        int l = tid + r*256;
        int i2 = l >> 5, d4 = l & 31;
        ((float4*)&xs[i2*132])[d4] = xg4[l];
    }
    __syncthreads();

    int kq = tid & 7, bq = tid >> 3;  // 8 k-groups x 32 bt-groups of 4
    float acc[4][8];
    #pragma unroll
    for (int a=0;a<4;a++){
        #pragma unroll
        for (int j=0;j<8;j++) acc[a][j]=0.f;
    }
    #pragma unroll 4
    for (int d4 = 0; d4 < 32; ++d4) {
        float4 xa[4], wb[8];
        #pragma unroll
        for (int a=0;a<4;a++) xa[a] = ((const float4*)&xs[(bq*4+a)*132])[d4];
        #pragma unroll
        for (int j=0;j<8;j++) wb[j] = ((const float4*)&ws[(kq+8*j)*132])[d4];
        #pragma unroll
        for (int a=0;a<4;a++){
            #pragma unroll
            for (int j=0;j<8;j++){
                acc[a][j] += xa[a].x*wb[j].x + xa[a].y*wb[j].y
                           + xa[a].z*wb[j].z + xa[a].w*wb[j].w;
            }
        }
    }

    // wait for sigma (GEMM above overlapped block 0's work)
    if (tid == 0) {
        int st;
        do { st = atomicAdd(&g_sflag, 0); if (!st) __nanosleep(100); } while (!st);
    }
    __syncthreads();
    __threadfence();
    float siginv = *(volatile float*)&g_sigma_inv;

    __syncthreads();   // done reading xs/ws; reuse as a/u stage

    float* sAr = sm;                  // [128][65]
    float* sAi = sm + 128*65;
    float* sU  = sm + 2*128*65;

    #pragma unroll
    for (int a=0;a<4;a++) {
        int tl = bq*4 + a;            // local t in [0,128)
        int bt = bt0 + tl;
        float dtv = dt[bt];
        float tm  = tau_mod[bt];
        #pragma unroll
        for (int j=0;j<8;j++) {
            int k2 = kq + 8*j;
            int idx = bt*64 + k2;
            float u  = siginv*acc[a][j] + bvec[k2];
            float ad = g_alpha0[k2] * __expf(alpha_mod[idx] + tm) * dtv;
            float th = g_omega0[k2] * __expf(omega_mod[idx] + tm) * dtv;
            float rho = 1.f - ad*(1.f - ad*(0.5f - 0.16666667f*ad));
            float t2  = th*th;
            float cs  = 1.f - 0.5f*t2*(1.f - 0.083333336f*t2);
            float sn  = th*(1.f - 0.16666667f*t2);
            sAr[tl*65 + k2] = rho*cs;
            sAi[tl*65 + k2] = rho*sn;
            sU [tl*65 + k2] = u;
        }
    }
    __syncthreads();

    // local sub-chunk scans: 4 chunks x 64 lanes, 32 steps
    int cc = tid >> 6;
    int k  = tid & 63;
    {
        int tb = cc*32;
        float zr=0.f, zi=0.f, Ar=1.f, Ai=0.f;
        #pragma unroll 8
        for (int i = 0; i < 32; ++i) {
            float ar = sAr[(tb+i)*65 + k];
            float ai = sAi[(tb+i)*65 + k];
            float u  = sU [(tb+i)*65 + k];
            float nr = ar*zr - ai*zi + u;
            float ni = ai*zr + ar*zi;
            zr = nr; zi = ni;
            float br = ar*Ar - ai*Ai;
            float bi = ai*Ar + ar*Ai;
            Ar = br; Ai = bi;
        }
        sSum[cc*64 + k] = make_float4(Ar, Ai, zr, zi);
    }
    __syncthreads();

    // block aggregate (lanes 0..63) then publish / lookback
    float bAr=1.f, bAi=0.f, bZr=0.f, bZi=0.f;
    if (tid < 64) {
        #pragma unroll
        for (int j = 0; j < 4; ++j) {
            float4 s4 = sSum[j*64 + tid];
            float nzr = s4.x*bZr - s4.y*bZi + s4.z;
            float nzi = s4.y*bZr + s4.x*bZi + s4.w;
            float nar = s4.x*bAr - s4.y*bAi;
            float nai = s4.y*bAr + s4.x*bAi;
            bZr=nzr; bZi=nzi; bAr=nar; bAi=nai;
        }
    }

    float pr = 0.f, pi = 0.f;
    if (p == 0) {
        if (tid < 64) {
            g_bZI[lin*Kk + tid] = make_float2(bZr, bZi);
            __threadfence();
        }
        __syncthreads();
        if (tid == 0) atomicExch(&g_bst[lin], 2);
    } else {
        if (tid < 64) {
            g_bA[lin*Kk + tid] = make_float2(bAr, bAi);
            g_bZ[lin*Kk + tid] = make_float2(bZr, bZi);
            __threadfence();
        }
        __syncthreads();
        if (tid == 0) atomicExch(&g_bst[lin], 1);

        float Ra=1.f, Rb=0.f, Rzr=0.f, Rzi=0.f;
        int w = lin - 1;
        int wend = lin - p;
        for (;;) {
            if (tid == 0) {
                int st;
                do { st = atomicAdd(&g_bst[w], 0); if (!st) __nanosleep(60); } while (!st);
                s_st = st;
            }
            __syncthreads();
            int st = s_st;
            __syncthreads();
            if (tid < 64) {
                __threadfence();
                if (st == 2) {
                    float2 z2 = __ldcg(&g_bZI[w*Kk + tid]);
                    pr = Ra*z2.x - Rb*z2.y + Rzr;
                    pi = Rb*z2.x + Ra*z2.y + Rzi;
                } else {
                    float2 Aw = __ldcg(&g_bA[w*Kk + tid]);
                    float2 Zw = __ldcg(&g_bZ[w*Kk + tid]);
                    float nzr = Ra*Zw.x - Rb*Zw.y + Rzr;
                    float nzi = Rb*Zw.x + Ra*Zw.y + Rzi;
                    float nar = Ra*Aw.x - Rb*Aw.y;
                    float nai = Ra*Aw.y + Rb*Aw.x;
                    Rzr=nzr; Rzi=nzi; Ra=nar; Rb=nai;
                }
            }
            if (st == 2) break;
            --w;
            if (w < wend) { if (tid < 64) { pr = Rzr; pi = Rzi; } break; }
        }
        if (tid < 64) {
            float zir = bAr*pr - bAi*pi + bZr;
            float zii = bAi*pr + bAr*pi + bZi;
            g_bZI[lin*Kk + tid] = make_float2(zir, zii);
            __threadfence();
        }
        __syncthreads();
        if (tid == 0) atomicExch(&g_bst[lin], 2);
    }

    if (tid < 64) sPre[tid] = make_float2(pr, pi);
    __syncthreads();

    // final scan with correct init, write output
    {
        float2 z0 = sPre[k];
        float zr = z0.x, zi = z0.y;
        #pragma unroll
        for (int j = 0; j < 3; ++j) {
            if (j < cc) {
                float4 s4 = sSum[j*64 + k];
                float nr = s4.x*zr - s4.y*zi + s4.z;
                float ni = s4.y*zr + s4.x*zi + s4.w;
                zr = nr; zi = ni;
            }
        }
        int tb = cc*32;
        float* outb = out + (size_t)(bt0 + tb)*128;
        #pragma unroll 8
        for (int i = 0; i < 32; ++i) {
            float ar = sAr[(tb+i)*65 + k];
            float ai = sAi[(tb+i)*65 + k];
            float u  = sU [(tb+i)*65 + k];
            float nr = ar*zr - ai*zi + u;
            float ni = ai*zr + ar*zi;
            zr = nr; zi = ni;
            outb[i*128 + k]      = zr;   // C
            outb[i*128 + 64 + k] = zi;   // S
        }
    }
}

extern "C" void kernel_launch(void* const* d_in, const int* in_sizes, int n_in,
                              void* d_out, int out_size)
{
    const float* x          = (const float*)d_in[0];
    const float* dt         = (const float*)d_in[1];
    const float* alpha_mod  = (const float*)d_in[2];
    const float* omega_mod  = (const float*)d_in[3];
    const float* tau_mod    = (const float*)d_in[4];
    const float* s_real_raw = (const float*)d_in[5];
    const float* s_imag     = (const float*)d_in[6];
    const float* tau_raw    = (const float*)d_in[7];
    const float* W          = (const float*)d_in[8];
    const float* bvec       = (const float*)d_in[9];
    float* out = (float*)d_out;

    cudaFuncSetAttribute(k_fused, cudaFuncAttributeMaxDynamicSharedMemorySize, 101376);

    k_init<<<1, 512>>>();
    k_fused<<<NBLK + 1, 256, 101376>>>(x, dt, alpha_mod, omega_mod, tau_mod,
                                       bvec, W, s_real_raw, s_imag, tau_raw, out);
}